// round 1
// baseline (speedup 1.0000x reference)
#include <cuda_runtime.h>
#include <math.h>
#include <stdint.h>

// Problem dims (fixed by the dataset)
constexpr int BATCH = 16384;
constexpr int D_IN  = 2048;
constexpr int H1D   = 1024;
constexpr int H2D   = 512;
constexpr int DLAT  = 256;
constexpr int KCODE = 1024;

// ---------------------------------------------------------------------------
// Scratch (allocation-free contract: __device__ globals)
// ---------------------------------------------------------------------------
__device__ float g_h1[(size_t)BATCH * H1D];     // enc h1 / VQ scores / dec h1 (reused)
__device__ float g_h2[(size_t)BATCH * H2D];     // enc h2 / dec h2 (reused)
__device__ float g_res[(size_t)BATCH * DLAT];   // z after LN, then running residual
__device__ float g_zq[(size_t)BATCH * DLAT];    // z_q_total
__device__ float g_vloss[BATCH];                // accumulated VQ losses
__device__ int   g_idx[BATCH * 3];              // code indices
__device__ float g_cbn[3 * KCODE];              // ||c||^2 per code per stage

// ---------------------------------------------------------------------------
// Generic fp32 SGEMM: C[M,N] = act(A[M,K] @ B + bias)
//   TRANSB=0: B is [K,N] row-major.  TRANSB=1: B is [N,K] row-major.
// 128x128 tile, BK=8, 256 threads, 8x8 per thread.
// All dims assumed multiples of tile sizes (true for this problem).
// ---------------------------------------------------------------------------
template <bool TRANSB, bool RELU, bool HASBIAS>
__global__ __launch_bounds__(256)
void sgemm(const float* __restrict__ A, const float* __restrict__ B,
           const float* __restrict__ bias, float* __restrict__ C,
           int M, int N, int Kd)
{
    __shared__ float As[8][132];
    __shared__ float Bs[8][132];

    const int tid = threadIdx.x;
    const int tx = tid & 15;       // 0..15 -> 8 output cols each
    const int ty = tid >> 4;       // 0..15 -> 8 output rows each
    const int bx = blockIdx.x;     // N tile
    const int by = blockIdx.y;     // M tile

    float acc[8][8];
#pragma unroll
    for (int i = 0; i < 8; i++)
#pragma unroll
        for (int j = 0; j < 8; j++) acc[i][j] = 0.0f;

    const float* Ab = A + (size_t)(by * 128) * Kd;

    for (int k0 = 0; k0 < Kd; k0 += 8) {
        // A tile: 128 rows x 8 k, transposed into As[k][row]
        {
            int r  = tid >> 1;
            int kk = (tid & 1) * 4;
            float4 v = *(const float4*)(Ab + (size_t)r * Kd + k0 + kk);
            As[kk + 0][r] = v.x; As[kk + 1][r] = v.y;
            As[kk + 2][r] = v.z; As[kk + 3][r] = v.w;
        }
        if (!TRANSB) {
            int kk = tid >> 5;
            int n  = (tid & 31) * 4;
            float4 v = *(const float4*)(B + (size_t)(k0 + kk) * N + bx * 128 + n);
            Bs[kk][n + 0] = v.x; Bs[kk][n + 1] = v.y;
            Bs[kk][n + 2] = v.z; Bs[kk][n + 3] = v.w;
        } else {
            int n  = tid >> 1;
            int kk = (tid & 1) * 4;
            float4 v = *(const float4*)(B + (size_t)(bx * 128 + n) * Kd + k0 + kk);
            Bs[kk + 0][n] = v.x; Bs[kk + 1][n] = v.y;
            Bs[kk + 2][n] = v.z; Bs[kk + 3][n] = v.w;
        }
        __syncthreads();

#pragma unroll
        for (int k = 0; k < 8; k++) {
            float ra[8], rb[8];
#pragma unroll
            for (int i = 0; i < 8; i++) ra[i] = As[k][ty * 8 + i];
#pragma unroll
            for (int j = 0; j < 8; j++) rb[j] = Bs[k][tx * 8 + j];
#pragma unroll
            for (int i = 0; i < 8; i++)
#pragma unroll
                for (int j = 0; j < 8; j++)
                    acc[i][j] = fmaf(ra[i], rb[j], acc[i][j]);
        }
        __syncthreads();
    }

    // Epilogue
#pragma unroll
    for (int i = 0; i < 8; i++) {
        size_t row = (size_t)(by * 128 + ty * 8 + i);
        float* Cr = C + row * N + bx * 128 + tx * 8;
#pragma unroll
        for (int j = 0; j < 8; j += 4) {
            float4 v;
            float b0 = 0.f, b1 = 0.f, b2 = 0.f, b3 = 0.f;
            if (HASBIAS) {
                const float* bp = bias + bx * 128 + tx * 8 + j;
                b0 = bp[0]; b1 = bp[1]; b2 = bp[2]; b3 = bp[3];
            }
            v.x = acc[i][j + 0] + b0;
            v.y = acc[i][j + 1] + b1;
            v.z = acc[i][j + 2] + b2;
            v.w = acc[i][j + 3] + b3;
            if (RELU) {
                v.x = fmaxf(v.x, 0.f); v.y = fmaxf(v.y, 0.f);
                v.z = fmaxf(v.z, 0.f); v.w = fmaxf(v.w, 0.f);
            }
            *(float4*)(Cr + j) = v;
        }
    }
}

// ---------------------------------------------------------------------------
// LayerNorm over DLAT=256, warp per row (8 rows / 256-thread block)
// ---------------------------------------------------------------------------
__global__ __launch_bounds__(256)
void ln_kernel(float* __restrict__ z, const float* __restrict__ g,
               const float* __restrict__ b)
{
    int row  = blockIdx.x * 8 + (threadIdx.x >> 5);
    int lane = threadIdx.x & 31;
    float* zr = z + (size_t)row * DLAT;

    float v[8];
    float s = 0.f;
#pragma unroll
    for (int i = 0; i < 8; i++) { v[i] = zr[lane + 32 * i]; s += v[i]; }
#pragma unroll
    for (int o = 16; o; o >>= 1) s += __shfl_xor_sync(0xffffffffu, s, o);
    float mu = s * (1.0f / 256.0f);

    float s2 = 0.f;
#pragma unroll
    for (int i = 0; i < 8; i++) { float d = v[i] - mu; s2 += d * d; }
#pragma unroll
    for (int o = 16; o; o >>= 1) s2 += __shfl_xor_sync(0xffffffffu, s2, o);
    float var = s2 * (1.0f / 256.0f);
    float rs  = 1.0f / sqrtf(var + 1e-5f);

#pragma unroll
    for (int i = 0; i < 8; i++) {
        int col = lane + 32 * i;
        zr[col] = (v[i] - mu) * rs * g[col] + b[col];
    }
}

// ---------------------------------------------------------------------------
// Codebook row norms: warp per code, 3072 codes total
// ---------------------------------------------------------------------------
__global__ __launch_bounds__(256)
void cbnorm_kernel(const float* __restrict__ cb0, const float* __restrict__ cb1,
                   const float* __restrict__ cb2, float* __restrict__ cbn)
{
    int code = blockIdx.x * 8 + (threadIdx.x >> 5);   // 0..3071
    int lane = threadIdx.x & 31;
    const float* cb = (code < KCODE) ? cb0 : (code < 2 * KCODE ? cb1 : cb2);
    const float* c  = cb + (size_t)(code & (KCODE - 1)) * DLAT;
    float s = 0.f;
#pragma unroll
    for (int i = 0; i < 8; i++) { float v = c[lane + 32 * i]; s += v * v; }
#pragma unroll
    for (int o = 16; o; o >>= 1) s += __shfl_xor_sync(0xffffffffu, s, o);
    if (lane == 0) cbn[code] = s;
}

// ---------------------------------------------------------------------------
// Argmin over K=1024 distances d = ||r||^2 - 2 r.c + ||c||^2 (first-min ties)
// scores[row, n] = r.c (precomputed GEMM). Warp per row.
// ---------------------------------------------------------------------------
__global__ __launch_bounds__(256)
void argmin_kernel(const float* __restrict__ res, const float* __restrict__ scores,
                   const float* __restrict__ cbn, int* __restrict__ idx_out, int stage)
{
    int row  = blockIdx.x * 8 + (threadIdx.x >> 5);
    int lane = threadIdx.x & 31;

    const float* r = res + (size_t)row * DLAT;
    float s = 0.f;
#pragma unroll
    for (int i = 0; i < 8; i++) { float v = r[lane + 32 * i]; s += v * v; }
#pragma unroll
    for (int o = 16; o; o >>= 1) s += __shfl_xor_sync(0xffffffffu, s, o);
    float rnorm = s;  // all lanes

    const float* sr = scores + (size_t)row * KCODE;
    float best = INFINITY;
    int bi = 0;
#pragma unroll 4
    for (int n = lane; n < KCODE; n += 32) {
        float d = (rnorm - 2.0f * sr[n]) + cbn[n];
        if (d < best) { best = d; bi = n; }   // ascending n -> first occurrence
    }
#pragma unroll
    for (int o = 16; o; o >>= 1) {
        float ov = __shfl_xor_sync(0xffffffffu, best, o);
        int   oi = __shfl_xor_sync(0xffffffffu, bi, o);
        if (ov < best || (ov == best && oi < bi)) { best = ov; bi = oi; }
    }
    if (lane == 0) idx_out[row * 3 + stage] = bi;
}

// ---------------------------------------------------------------------------
// VQ update: straight-through z_q, residual, z_q_total, stage loss.
// Replicates JAX numerics: t = e - r; z_q = r + t; res' = r - z_q;
// loss = m + 0.25*m with m = mean((r-e)^2).
// ---------------------------------------------------------------------------
__global__ __launch_bounds__(256)
void vq_update(float* __restrict__ res, float* __restrict__ zq,
               float* __restrict__ vloss, const float* __restrict__ cb,
               const int* __restrict__ idx, int stage)
{
    int row  = blockIdx.x * 8 + (threadIdx.x >> 5);
    int lane = threadIdx.x & 31;

    int id = idx[row * 3 + stage];
    const float* c = cb + (size_t)id * DLAT;
    float* r = res + (size_t)row * DLAT;
    float* q = zq + (size_t)row * DLAT;

    float se = 0.f;
#pragma unroll
    for (int i = 0; i < 8; i++) {
        int col = lane + 32 * i;
        float rv = r[col];
        float ev = c[col];
        float diff = rv - ev;
        se += diff * diff;
        float t   = ev - rv;       // sg(e - r)
        float zqe = rv + t;        // straight-through z_q
        r[col] = rv - zqe;         // residual - sg(z_q)
        q[col] = (stage == 0) ? zqe : (q[col] + zqe);
    }
#pragma unroll
    for (int o = 16; o; o >>= 1) se += __shfl_xor_sync(0xffffffffu, se, o);
    if (lane == 0) {
        float m = se * (1.0f / 256.0f);
        float l = m + 0.25f * m;
        vloss[row] = (stage == 0) ? l : (vloss[row] + l);
    }
}

// ---------------------------------------------------------------------------
// Finalize: recon loss per row, total loss, idx -> float output
// ---------------------------------------------------------------------------
__global__ __launch_bounds__(256)
void finalize_kernel(const float* __restrict__ x, const float* __restrict__ xhat,
                     const float* __restrict__ vloss, const int* __restrict__ idx,
                     float* __restrict__ out_loss, float* __restrict__ out_idx)
{
    int row  = blockIdx.x * 8 + (threadIdx.x >> 5);
    int lane = threadIdx.x & 31;

    const float* xr = x    + (size_t)row * D_IN;
    const float* hr = xhat + (size_t)row * D_IN;
    float s = 0.f;
#pragma unroll 8
    for (int i = 0; i < 64; i++) {
        int col = lane + 32 * i;
        float d = hr[col] - xr[col];
        s += d * d;
    }
#pragma unroll
    for (int o = 16; o; o >>= 1) s += __shfl_xor_sync(0xffffffffu, s, o);
    if (lane == 0) {
        float recon = s * (1.0f / 2048.0f);
        out_loss[row] = vloss[row] + recon;
    }
    if (lane < 3) out_idx[row * 3 + lane] = (float)idx[row * 3 + lane];
}

// ---------------------------------------------------------------------------
// Launch
// ---------------------------------------------------------------------------
extern "C" void kernel_launch(void* const* d_in, const int* in_sizes, int n_in,
                              void* d_out, int out_size)
{
    const float* x      = (const float*)d_in[0];
    const float* encW1  = (const float*)d_in[1];
    const float* encb1  = (const float*)d_in[2];
    const float* encW2  = (const float*)d_in[3];
    const float* encb2  = (const float*)d_in[4];
    const float* encW3  = (const float*)d_in[5];
    const float* encb3  = (const float*)d_in[6];
    const float* ln_g   = (const float*)d_in[7];
    const float* ln_b   = (const float*)d_in[8];
    const float* cb0    = (const float*)d_in[9];
    const float* cb1    = (const float*)d_in[10];
    const float* cb2    = (const float*)d_in[11];
    const float* decW1  = (const float*)d_in[12];
    const float* decb1  = (const float*)d_in[13];
    const float* decW2  = (const float*)d_in[14];
    const float* decb2  = (const float*)d_in[15];
    const float* decW3  = (const float*)d_in[16];
    const float* decb3  = (const float*)d_in[17];

    float *h1, *h2, *res, *zq, *vloss, *cbn;
    int* idx;
    cudaGetSymbolAddress((void**)&h1, g_h1);
    cudaGetSymbolAddress((void**)&h2, g_h2);
    cudaGetSymbolAddress((void**)&res, g_res);
    cudaGetSymbolAddress((void**)&zq, g_zq);
    cudaGetSymbolAddress((void**)&vloss, g_vloss);
    cudaGetSymbolAddress((void**)&cbn, g_cbn);
    cudaGetSymbolAddress((void**)&idx, g_idx);

    float* xhat     = (float*)d_out;
    float* out_loss = xhat + (size_t)BATCH * D_IN;
    float* out_idx  = out_loss + BATCH;

    const dim3 blk(256);
    const int rowBlocks = BATCH / 128;   // 128
    const int warpGrid  = BATCH / 8;     // 2048

    // codebook norms
    cbnorm_kernel<<<3 * KCODE / 8, blk>>>(cb0, cb1, cb2, cbn);

    // encoder
    sgemm<false, true,  true><<<dim3(H1D / 128, rowBlocks), blk>>>(x,  encW1, encb1, h1,  BATCH, H1D,  D_IN);
    sgemm<false, true,  true><<<dim3(H2D / 128, rowBlocks), blk>>>(h1, encW2, encb2, h2,  BATCH, H2D,  H1D);
    sgemm<false, false, true><<<dim3(DLAT / 128, rowBlocks), blk>>>(h2, encW3, encb3, res, BATCH, DLAT, H2D);

    // layernorm
    ln_kernel<<<warpGrid, blk>>>(res, ln_g, ln_b);

    // residual VQ (scores reuse h1 scratch)
    for (int s = 0; s < 3; s++) {
        const float* cb = (s == 0) ? cb0 : (s == 1 ? cb1 : cb2);
        sgemm<true, false, false><<<dim3(KCODE / 128, rowBlocks), blk>>>(res, cb, nullptr, h1, BATCH, KCODE, DLAT);
        argmin_kernel<<<warpGrid, blk>>>(res, h1, cbn + s * KCODE, idx, s);
        vq_update<<<warpGrid, blk>>>(res, zq, vloss, cb, idx, s);
    }

    // decoder (h2, h1 reused; x_hat straight into d_out)
    sgemm<false, true,  true><<<dim3(H2D / 128, rowBlocks), blk>>>(zq, decW1, decb1, h2,   BATCH, H2D,  DLAT);
    sgemm<false, true,  true><<<dim3(H1D / 128, rowBlocks), blk>>>(h2, decW2, decb2, h1,   BATCH, H1D,  H2D);
    sgemm<false, false, true><<<dim3(D_IN / 128, rowBlocks), blk>>>(h1, decW3, decb3, xhat, BATCH, D_IN, H1D);

    // losses + idx writeout
    finalize_kernel<<<warpGrid, blk>>>(x, xhat, vloss, idx, out_loss, out_idx);
}

// round 3
// speedup vs baseline: 1.6385x; 1.6385x over previous
#include <cuda_runtime.h>
#include <math.h>
#include <stdint.h>

// Problem dims (fixed by the dataset)
constexpr int BATCH = 16384;
constexpr int D_IN  = 2048;
constexpr int H1D   = 1024;
constexpr int H2D   = 512;
constexpr int DLAT  = 256;
constexpr int KCODE = 1024;

// ---------------------------------------------------------------------------
// Scratch (allocation-free contract: __device__ globals)
// ---------------------------------------------------------------------------
__device__ float g_h1[(size_t)BATCH * H1D];     // enc h1 / VQ scores / dec h1
__device__ float g_h2[(size_t)BATCH * H2D];     // enc h2 / dec h2
__device__ float g_res[(size_t)BATCH * DLAT];   // z after LN, then running residual
__device__ float g_zq[(size_t)BATCH * DLAT];    // z_q_total
__device__ float g_vloss[BATCH];
__device__ int   g_idx[BATCH * 3];
__device__ float g_cbn[3 * KCODE];
// transposed weights, [N,K] row-major (K-major rows for the B operand)
__device__ float g_w1t[(size_t)H1D * D_IN];
__device__ float g_w2t[(size_t)H2D * H1D];
__device__ float g_w3t[(size_t)DLAT * H2D];
__device__ float g_d1t[(size_t)H2D * DLAT];
__device__ float g_d2t[(size_t)H1D * H2D];
__device__ float g_d3t[(size_t)D_IN * H1D];

// ---------------------------------------------------------------------------
// Helpers
// ---------------------------------------------------------------------------
__device__ __forceinline__ float tf32_rna(float a) {
    uint32_t r;
    asm("cvt.rna.tf32.f32 %0, %1;" : "=r"(r) : "f"(a));
    return __uint_as_float(r);
}

__device__ __forceinline__ float4 cvt4(float4 v) {
    float4 h;
    h.x = tf32_rna(v.x); h.y = tf32_rna(v.y);
    h.z = tf32_rna(v.z); h.w = tf32_rna(v.w);
    return h;
}

__device__ __forceinline__ float4 sub_cvt4(float4 v, float4 h) {
    float4 l;
    l.x = tf32_rna(v.x - h.x); l.y = tf32_rna(v.y - h.y);
    l.z = tf32_rna(v.z - h.z); l.w = tf32_rna(v.w - h.w);
    return l;
}

// m16n8k8 tf32 MMA (row.col), fp32 accumulate
__device__ __forceinline__ void mma8(float d[4], const float a[4], const float b[2]) {
    asm volatile(
        "mma.sync.aligned.m16n8k8.row.col.f32.tf32.tf32.f32 "
        "{%0,%1,%2,%3}, {%4,%5,%6,%7}, {%8,%9}, {%0,%1,%2,%3};\n"
        : "+f"(d[0]), "+f"(d[1]), "+f"(d[2]), "+f"(d[3])
        : "r"(__float_as_uint(a[0])), "r"(__float_as_uint(a[1])),
          "r"(__float_as_uint(a[2])), "r"(__float_as_uint(a[3])),
          "r"(__float_as_uint(b[0])), "r"(__float_as_uint(b[1])));
}

// A fragment (16x8) from SW128-swizzled tile (128B rows of 32 floats).
// a0:(row,col) a1:(row+8,col) a2:(row,col+4) a3:(row+8,col+4)
__device__ __forceinline__ void ld_afrag(const char* base, int mt, int ks,
                                         int lane, float f[4]) {
    uint32_t row = mt * 16 + (lane >> 2);
    uint32_t c0  = (ks * 8 + (lane & 3)) * 4;
    uint32_t s   = (row & 7u) << 4;          // (row+8)&7 == row&7
    const char* pr0 = base + row * 128;
    const char* pr1 = pr0 + 8 * 128;
    f[0] = *(const float*)(pr0 + (c0 ^ s));
    f[1] = *(const float*)(pr1 + (c0 ^ s));
    f[2] = *(const float*)(pr0 + ((c0 + 16) ^ s));
    f[3] = *(const float*)(pr1 + ((c0 + 16) ^ s));
}

// B fragment (8x8, B^T stored [n][k]): b0:(k=lane&3, n=lane>>2) b1:(k+4, n)
__device__ __forceinline__ void ld_bfrag(const char* base, int nt, int ks,
                                         int lane, float f[2]) {
    uint32_t row = nt * 8 + (lane >> 2);     // n
    uint32_t c0  = (ks * 8 + (lane & 3)) * 4;
    uint32_t s   = (row & 7u) << 4;
    const char* pr = base + row * 128;
    f[0] = *(const float*)(pr + (c0 ^ s));
    f[1] = *(const float*)(pr + ((c0 + 16) ^ s));
}

// ---------------------------------------------------------------------------
// tf32 mma.sync GEMM: C[M,N] = act(A[M,K] @ B^T + bias)
//   A: fp32 [M,K] row-major. B: fp32 [N,K] row-major.
//   NTERMS==3: split tf32 (hi*hi + hi*lo + lo*hi) ~ fp32 accuracy
//   NTERMS==1: single-pass tf32
// Tile 128x128, BK=32, 256 threads, 8 warps (2 m x 4 n), 64x32 per warp.
// SMEM per stage: A_hi(16K) B_hi(16K) [A_lo(16K) B_lo(16K)], 2 stages.
// ---------------------------------------------------------------------------
template <int NTERMS, bool RELU, bool HASBIAS>
__global__ __launch_bounds__(256, 1)
void mma_gemm(const float* __restrict__ A, const float* __restrict__ B,
              const float* __restrict__ bias, float* __restrict__ C,
              int N, int Kd)
{
    extern __shared__ char smem[];
    constexpr int TILEB = 16384;
    constexpr int STAGE = (NTERMS == 3) ? 65536 : 32768;

    const int tid  = threadIdx.x;
    const int wid  = tid >> 5;
    const int lane = tid & 31;
    const int wm   = wid & 1;       // 0..1 -> 64 rows
    const int wn   = wid >> 1;      // 0..3 -> 32 cols

    const int nk = Kd >> 5;
    const float* Ag = A + (size_t)(blockIdx.y * 128) * Kd;
    const float* Bg = B + (size_t)(blockIdx.x * 128) * Kd;

    // staging role: thread -> (row r, 16-float half hf of the 32-wide k chunk)
    const int r  = tid >> 1;
    const int hf = tid & 1;
    const uint32_t rowoff = (uint32_t)r * 128;
    const uint32_t cbase  = (uint32_t)hf * 64;
    const uint32_t sw     = (r & 7u) << 4;

    float acc[4][4][4];
#pragma unroll
    for (int i = 0; i < 4; i++)
#pragma unroll
        for (int j = 0; j < 4; j++)
#pragma unroll
            for (int q = 0; q < 4; q++) acc[i][j][q] = 0.0f;

    float4 va[4], vb[4];

    auto ldg = [&](int k0) {
        const float4* pa = (const float4*)(Ag + (size_t)r * Kd + k0 * 32 + hf * 16);
        const float4* pb = (const float4*)(Bg + (size_t)r * Kd + k0 * 32 + hf * 16);
#pragma unroll
        for (int j = 0; j < 4; j++) { va[j] = pa[j]; vb[j] = pb[j]; }
    };

    auto stage_store = [&](int s) {
        char* st = smem + s * STAGE;
#pragma unroll
        for (int j = 0; j < 4; j++) {
            uint32_t off = rowoff + ((cbase + j * 16) ^ sw);
            float4 ha = cvt4(va[j]);
            float4 hb = cvt4(vb[j]);
            *(float4*)(st + off)         = ha;
            *(float4*)(st + TILEB + off) = hb;
            if (NTERMS == 3) {
                *(float4*)(st + 2 * TILEB + off) = sub_cvt4(va[j], ha);
                *(float4*)(st + 3 * TILEB + off) = sub_cvt4(vb[j], hb);
            }
        }
    };

    ldg(0);
    stage_store(0);
    __syncthreads();

    for (int k0 = 0; k0 < nk; k0++) {
        if (k0 + 1 < nk) ldg(k0 + 1);

        const char* st = smem + (k0 & 1) * STAGE;
#pragma unroll
        for (int ks = 0; ks < 4; ks++) {
            float ah[4][4], bh[4][2];
            float al[4][4], bl[4][2];
#pragma unroll
            for (int mt = 0; mt < 4; mt++) {
                ld_afrag(st, wm * 4 + mt, ks, lane, ah[mt]);
                if (NTERMS == 3) ld_afrag(st + 2 * TILEB, wm * 4 + mt, ks, lane, al[mt]);
            }
#pragma unroll
            for (int nt = 0; nt < 4; nt++) {
                ld_bfrag(st + TILEB, wn * 4 + nt, ks, lane, bh[nt]);
                if (NTERMS == 3) ld_bfrag(st + 3 * TILEB, wn * 4 + nt, ks, lane, bl[nt]);
            }
#pragma unroll
            for (int mt = 0; mt < 4; mt++)
#pragma unroll
                for (int nt = 0; nt < 4; nt++) {
                    mma8(acc[mt][nt], ah[mt], bh[nt]);
                    if (NTERMS == 3) {
                        mma8(acc[mt][nt], ah[mt], bl[nt]);
                        mma8(acc[mt][nt], al[mt], bh[nt]);
                    }
                }
        }

        if (k0 + 1 < nk) stage_store((k0 + 1) & 1);
        __syncthreads();
    }

    // ---- epilogue ----
    const int row0 = blockIdx.y * 128 + wm * 64 + (lane >> 2);
    const int col0 = blockIdx.x * 128 + wn * 32 + (lane & 3) * 2;
#pragma unroll
    for (int mt = 0; mt < 4; mt++) {
#pragma unroll
        for (int nt = 0; nt < 4; nt++) {
            int rr = row0 + mt * 16;
            int cc = col0 + nt * 8;
            float b0 = 0.f, b1 = 0.f;
            if (HASBIAS) { b0 = __ldg(bias + cc); b1 = __ldg(bias + cc + 1); }
            float2 v0, v1;
            v0.x = acc[mt][nt][0] + b0; v0.y = acc[mt][nt][1] + b1;
            v1.x = acc[mt][nt][2] + b0; v1.y = acc[mt][nt][3] + b1;
            if (RELU) {
                v0.x = fmaxf(v0.x, 0.f); v0.y = fmaxf(v0.y, 0.f);
                v1.x = fmaxf(v1.x, 0.f); v1.y = fmaxf(v1.y, 0.f);
            }
            *(float2*)(C + (size_t)rr * N + cc)       = v0;
            *(float2*)(C + (size_t)(rr + 8) * N + cc) = v1;
        }
    }
}

// ---------------------------------------------------------------------------
// Tiled transpose: W[K,N] -> T[N,K]
// ---------------------------------------------------------------------------
__global__ __launch_bounds__(256)
void transpose_kernel(const float* __restrict__ W, float* __restrict__ T,
                      int K, int N)
{
    __shared__ float tile[32][33];
    int n0 = blockIdx.x * 32;
    int k0 = blockIdx.y * 32;
#pragma unroll
    for (int i = 0; i < 32; i += 8)
        tile[threadIdx.y + i][threadIdx.x] =
            W[(size_t)(k0 + threadIdx.y + i) * N + n0 + threadIdx.x];
    __syncthreads();
#pragma unroll
    for (int i = 0; i < 32; i += 8)
        T[(size_t)(n0 + threadIdx.y + i) * K + k0 + threadIdx.x] =
            tile[threadIdx.x][threadIdx.y + i];
}

// ---------------------------------------------------------------------------
// LayerNorm over DLAT=256, warp per row
// ---------------------------------------------------------------------------
__global__ __launch_bounds__(256)
void ln_kernel(float* __restrict__ z, const float* __restrict__ g,
               const float* __restrict__ b)
{
    int row  = blockIdx.x * 8 + (threadIdx.x >> 5);
    int lane = threadIdx.x & 31;
    float* zr = z + (size_t)row * DLAT;

    float v[8];
    float s = 0.f;
#pragma unroll
    for (int i = 0; i < 8; i++) { v[i] = zr[lane + 32 * i]; s += v[i]; }
#pragma unroll
    for (int o = 16; o; o >>= 1) s += __shfl_xor_sync(0xffffffffu, s, o);
    float mu = s * (1.0f / 256.0f);

    float s2 = 0.f;
#pragma unroll
    for (int i = 0; i < 8; i++) { float d = v[i] - mu; s2 += d * d; }
#pragma unroll
    for (int o = 16; o; o >>= 1) s2 += __shfl_xor_sync(0xffffffffu, s2, o);
    float var = s2 * (1.0f / 256.0f);
    float rs  = 1.0f / sqrtf(var + 1e-5f);

#pragma unroll
    for (int i = 0; i < 8; i++) {
        int col = lane + 32 * i;
        zr[col] = (v[i] - mu) * rs * g[col] + b[col];
    }
}

// ---------------------------------------------------------------------------
// Codebook row norms: warp per code
// ---------------------------------------------------------------------------
__global__ __launch_bounds__(256)
void cbnorm_kernel(const float* __restrict__ cb0, const float* __restrict__ cb1,
                   const float* __restrict__ cb2, float* __restrict__ cbn)
{
    int code = blockIdx.x * 8 + (threadIdx.x >> 5);
    int lane = threadIdx.x & 31;
    const float* cb = (code < KCODE) ? cb0 : (code < 2 * KCODE ? cb1 : cb2);
    const float* c  = cb + (size_t)(code & (KCODE - 1)) * DLAT;
    float s = 0.f;
#pragma unroll
    for (int i = 0; i < 8; i++) { float v = c[lane + 32 * i]; s += v * v; }
#pragma unroll
    for (int o = 16; o; o >>= 1) s += __shfl_xor_sync(0xffffffffu, s, o);
    if (lane == 0) cbn[code] = s;
}

// ---------------------------------------------------------------------------
// Argmin over K=1024 distances, first-occurrence tie-break. Warp per row.
// ---------------------------------------------------------------------------
__global__ __launch_bounds__(256)
void argmin_kernel(const float* __restrict__ res, const float* __restrict__ scores,
                   const float* __restrict__ cbn, int* __restrict__ idx_out, int stage)
{
    int row  = blockIdx.x * 8 + (threadIdx.x >> 5);
    int lane = threadIdx.x & 31;

    const float* r = res + (size_t)row * DLAT;
    float s = 0.f;
#pragma unroll
    for (int i = 0; i < 8; i++) { float v = r[lane + 32 * i]; s += v * v; }
#pragma unroll
    for (int o = 16; o; o >>= 1) s += __shfl_xor_sync(0xffffffffu, s, o);
    float rnorm = s;

    const float* sr = scores + (size_t)row * KCODE;
    float best = INFINITY;
    int bi = 0;
#pragma unroll 4
    for (int n = lane; n < KCODE; n += 32) {
        float d = (rnorm - 2.0f * sr[n]) + cbn[n];
        if (d < best) { best = d; bi = n; }
    }
#pragma unroll
    for (int o = 16; o; o >>= 1) {
        float ov = __shfl_xor_sync(0xffffffffu, best, o);
        int   oi = __shfl_xor_sync(0xffffffffu, bi, o);
        if (ov < best || (ov == best && oi < bi)) { best = ov; bi = oi; }
    }
    if (lane == 0) idx_out[row * 3 + stage] = bi;
}

// ---------------------------------------------------------------------------
// VQ update (straight-through; replicates JAX numerics)
// ---------------------------------------------------------------------------
__global__ __launch_bounds__(256)
void vq_update(float* __restrict__ res, float* __restrict__ zq,
               float* __restrict__ vloss, const float* __restrict__ cb,
               const int* __restrict__ idx, int stage)
{
    int row  = blockIdx.x * 8 + (threadIdx.x >> 5);
    int lane = threadIdx.x & 31;

    int id = idx[row * 3 + stage];
    const float* c = cb + (size_t)id * DLAT;
    float* r = res + (size_t)row * DLAT;
    float* q = zq + (size_t)row * DLAT;

    float se = 0.f;
#pragma unroll
    for (int i = 0; i < 8; i++) {
        int col = lane + 32 * i;
        float rv = r[col];
        float ev = c[col];
        float diff = rv - ev;
        se += diff * diff;
        float t   = ev - rv;
        float zqe = rv + t;
        r[col] = rv - zqe;
        q[col] = (stage == 0) ? zqe : (q[col] + zqe);
    }
#pragma unroll
    for (int o = 16; o; o >>= 1) se += __shfl_xor_sync(0xffffffffu, se, o);
    if (lane == 0) {
        float m = se * (1.0f / 256.0f);
        float l = m + 0.25f * m;
        vloss[row] = (stage == 0) ? l : (vloss[row] + l);
    }
}

// ---------------------------------------------------------------------------
// Finalize: recon loss, total loss, idx -> float
// ---------------------------------------------------------------------------
__global__ __launch_bounds__(256)
void finalize_kernel(const float* __restrict__ x, const float* __restrict__ xhat,
                     const float* __restrict__ vloss, const int* __restrict__ idx,
                     float* __restrict__ out_loss, float* __restrict__ out_idx)
{
    int row  = blockIdx.x * 8 + (threadIdx.x >> 5);
    int lane = threadIdx.x & 31;

    const float* xr = x    + (size_t)row * D_IN;
    const float* hr = xhat + (size_t)row * D_IN;
    float s = 0.f;
#pragma unroll 8
    for (int i = 0; i < 64; i++) {
        int col = lane + 32 * i;
        float d = hr[col] - xr[col];
        s += d * d;
    }
#pragma unroll
    for (int o = 16; o; o >>= 1) s += __shfl_xor_sync(0xffffffffu, s, o);
    if (lane == 0) {
        float recon = s * (1.0f / 2048.0f);
        out_loss[row] = vloss[row] + recon;
    }
    if (lane < 3) out_idx[row * 3 + lane] = (float)idx[row * 3 + lane];
}

// ---------------------------------------------------------------------------
// Launch
// ---------------------------------------------------------------------------
extern "C" void kernel_launch(void* const* d_in, const int* in_sizes, int n_in,
                              void* d_out, int out_size)
{
    const float* x      = (const float*)d_in[0];
    const float* encW1  = (const float*)d_in[1];
    const float* encb1  = (const float*)d_in[2];
    const float* encW2  = (const float*)d_in[3];
    const float* encb2  = (const float*)d_in[4];
    const float* encW3  = (const float*)d_in[5];
    const float* encb3  = (const float*)d_in[6];
    const float* ln_g   = (const float*)d_in[7];
    const float* ln_b   = (const float*)d_in[8];
    const float* cb0    = (const float*)d_in[9];
    const float* cb1    = (const float*)d_in[10];
    const float* cb2    = (const float*)d_in[11];
    const float* decW1  = (const float*)d_in[12];
    const float* decb1  = (const float*)d_in[13];
    const float* decW2  = (const float*)d_in[14];
    const float* decb2  = (const float*)d_in[15];
    const float* decW3  = (const float*)d_in[16];
    const float* decb3  = (const float*)d_in[17];

    float *h1, *h2, *res, *zq, *vloss, *cbn;
    float *w1t, *w2t, *w3t, *d1t, *d2t, *d3t;
    int* idx;
    cudaGetSymbolAddress((void**)&h1, g_h1);
    cudaGetSymbolAddress((void**)&h2, g_h2);
    cudaGetSymbolAddress((void**)&res, g_res);
    cudaGetSymbolAddress((void**)&zq, g_zq);
    cudaGetSymbolAddress((void**)&vloss, g_vloss);
    cudaGetSymbolAddress((void**)&cbn, g_cbn);
    cudaGetSymbolAddress((void**)&idx, g_idx);
    cudaGetSymbolAddress((void**)&w1t, g_w1t);
    cudaGetSymbolAddress((void**)&w2t, g_w2t);
    cudaGetSymbolAddress((void**)&w3t, g_w3t);
    cudaGetSymbolAddress((void**)&d1t, g_d1t);
    cudaGetSymbolAddress((void**)&d2t, g_d2t);
    cudaGetSymbolAddress((void**)&d3t, g_d3t);

    float* xhat     = (float*)d_out;
    float* out_loss = xhat + (size_t)BATCH * D_IN;
    float* out_idx  = out_loss + BATCH;

    const int SMEM3 = 2 * 65536;   // 128 KB
    const int SMEM1 = 2 * 32768;   // 64 KB
    cudaFuncSetAttribute((const void*)mma_gemm<3, true,  true >, cudaFuncAttributeMaxDynamicSharedMemorySize, SMEM3);
    cudaFuncSetAttribute((const void*)mma_gemm<3, false, true >, cudaFuncAttributeMaxDynamicSharedMemorySize, SMEM3);
    cudaFuncSetAttribute((const void*)mma_gemm<3, false, false>, cudaFuncAttributeMaxDynamicSharedMemorySize, SMEM3);
    cudaFuncSetAttribute((const void*)mma_gemm<1, true,  true >, cudaFuncAttributeMaxDynamicSharedMemorySize, SMEM1);
    cudaFuncSetAttribute((const void*)mma_gemm<1, false, true >, cudaFuncAttributeMaxDynamicSharedMemorySize, SMEM1);

    const dim3 blk(256);
    const dim3 tblk(32, 8);
    const int MB = BATCH / 128;          // 128
    const int warpGrid = BATCH / 8;      // 2048

    // ---- prep: transpose weights to [N,K]; codebook norms ----
    transpose_kernel<<<dim3(H1D / 32, D_IN / 32), tblk>>>(encW1, w1t, D_IN, H1D);
    transpose_kernel<<<dim3(H2D / 32, H1D / 32), tblk>>>(encW2, w2t, H1D, H2D);
    transpose_kernel<<<dim3(DLAT / 32, H2D / 32), tblk>>>(encW3, w3t, H2D, DLAT);
    transpose_kernel<<<dim3(H2D / 32, DLAT / 32), tblk>>>(decW1, d1t, DLAT, H2D);
    transpose_kernel<<<dim3(H1D / 32, H2D / 32), tblk>>>(decW2, d2t, H2D, H1D);
    transpose_kernel<<<dim3(D_IN / 32, H1D / 32), tblk>>>(decW3, d3t, H1D, D_IN);
    cbnorm_kernel<<<3 * KCODE / 8, blk>>>(cb0, cb1, cb2, cbn);

    // ---- encoder (tf32x3 split = fp32 accuracy) ----
    mma_gemm<3, true,  true ><<<dim3(H1D / 128, MB), blk, SMEM3>>>(x,  w1t, encb1, h1,  H1D,  D_IN);
    mma_gemm<3, true,  true ><<<dim3(H2D / 128, MB), blk, SMEM3>>>(h1, w2t, encb2, h2,  H2D,  H1D);
    mma_gemm<3, false, true ><<<dim3(DLAT / 128, MB), blk, SMEM3>>>(h2, w3t, encb3, res, DLAT, H2D);

    ln_kernel<<<warpGrid, blk>>>(res, ln_g, ln_b);

    // ---- residual VQ (scores in h1 scratch) ----
    for (int s = 0; s < 3; s++) {
        const float* cb = (s == 0) ? cb0 : (s == 1 ? cb1 : cb2);
        mma_gemm<3, false, false><<<dim3(KCODE / 128, MB), blk, SMEM3>>>(res, cb, nullptr, h1, KCODE, DLAT);
        argmin_kernel<<<warpGrid, blk>>>(res, h1, cbn + s * KCODE, idx, s);
        vq_update<<<warpGrid, blk>>>(res, zq, vloss, cb, idx, s);
    }

    // ---- decoder (single-pass tf32; post-argmin, tolerance-safe) ----
    mma_gemm<1, true,  true ><<<dim3(H2D / 128, MB), blk, SMEM1>>>(zq, d1t, decb1, h2,   H2D,  DLAT);
    mma_gemm<1, true,  true ><<<dim3(H1D / 128, MB), blk, SMEM1>>>(h2, d2t, decb2, h1,   H1D,  H2D);
    mma_gemm<1, false, true ><<<dim3(D_IN / 128, MB), blk, SMEM1>>>(h1, d3t, decb3, xhat, D_IN, H1D);

    finalize_kernel<<<warpGrid, blk>>>(x, xhat, vloss, idx, out_loss, out_idx);
}

// round 4
// speedup vs baseline: 1.7428x; 1.0636x over previous
#include <cuda_runtime.h>
#include <math.h>
#include <stdint.h>

// Problem dims (fixed by the dataset)
constexpr int BATCH = 16384;
constexpr int D_IN  = 2048;
constexpr int H1D   = 1024;
constexpr int H2D   = 512;
constexpr int DLAT  = 256;
constexpr int KCODE = 1024;

// ---------------------------------------------------------------------------
// Scratch (allocation-free contract: __device__ globals)
// ---------------------------------------------------------------------------
__device__ float g_h1[(size_t)BATCH * H1D];     // enc h1 / VQ scores / dec h1
__device__ float g_h2[(size_t)BATCH * H2D];     // enc h2 / dec h2
__device__ float g_res[(size_t)BATCH * DLAT];   // z after LN, then running residual
__device__ float g_zq[(size_t)BATCH * DLAT];    // z_q_total
__device__ float g_vloss[BATCH];
__device__ int   g_idx[BATCH * 3];
__device__ float g_cbn[3 * KCODE];
// transposed weights, [N,K] row-major (K-major rows for the B operand)
__device__ float g_w1t[(size_t)H1D * D_IN];
__device__ float g_w2t[(size_t)H2D * H1D];
__device__ float g_w3t[(size_t)DLAT * H2D];
__device__ float g_d1t[(size_t)H2D * DLAT];
__device__ float g_d2t[(size_t)H1D * H2D];
__device__ float g_d3t[(size_t)D_IN * H1D];

// ---------------------------------------------------------------------------
// Helpers
// ---------------------------------------------------------------------------
__device__ __forceinline__ float tf32_rna(float a) {
    uint32_t r;
    asm("cvt.rna.tf32.f32 %0, %1;" : "=r"(r) : "f"(a));
    return __uint_as_float(r);
}

__device__ __forceinline__ float4 cvt4(float4 v) {
    float4 h;
    h.x = tf32_rna(v.x); h.y = tf32_rna(v.y);
    h.z = tf32_rna(v.z); h.w = tf32_rna(v.w);
    return h;
}

__device__ __forceinline__ float4 sub_cvt4(float4 v, float4 h) {
    float4 l;
    l.x = tf32_rna(v.x - h.x); l.y = tf32_rna(v.y - h.y);
    l.z = tf32_rna(v.z - h.z); l.w = tf32_rna(v.w - h.w);
    return l;
}

// m16n8k8 tf32 MMA (row.col), fp32 accumulate
__device__ __forceinline__ void mma8(float d[4], const float a[4], const float b[2]) {
    asm volatile(
        "mma.sync.aligned.m16n8k8.row.col.f32.tf32.tf32.f32 "
        "{%0,%1,%2,%3}, {%4,%5,%6,%7}, {%8,%9}, {%0,%1,%2,%3};\n"
        : "+f"(d[0]), "+f"(d[1]), "+f"(d[2]), "+f"(d[3])
        : "r"(__float_as_uint(a[0])), "r"(__float_as_uint(a[1])),
          "r"(__float_as_uint(a[2])), "r"(__float_as_uint(a[3])),
          "r"(__float_as_uint(b[0])), "r"(__float_as_uint(b[1])));
}

// Tiles are [128 rows][16 floats] = 64B rows, swizzle: byte col XOR (((row>>1)&3)<<4).
// A fragment (16x8): a0:(row,k) a1:(row+8,k) a2:(row,k+4) a3:(row+8,k+4)
__device__ __forceinline__ void ld_afrag(const char* base, int mt, int ks,
                                         int lane, float f[4]) {
    uint32_t row = mt * 16 + (lane >> 2);
    uint32_t c0  = (ks * 8 + (lane & 3)) * 4;
    uint32_t s   = ((row >> 1) & 3u) << 4;   // same for row and row+8
    const char* pr0 = base + row * 64;
    const char* pr1 = pr0 + 8 * 64;
    f[0] = *(const float*)(pr0 + (c0 ^ s));
    f[1] = *(const float*)(pr1 + (c0 ^ s));
    f[2] = *(const float*)(pr0 + ((c0 + 16) ^ s));
    f[3] = *(const float*)(pr1 + ((c0 + 16) ^ s));
}

// B fragment (8x8, B^T stored [n][k]): b0:(k=lane&3, n=lane>>2) b1:(k+4, n)
__device__ __forceinline__ void ld_bfrag(const char* base, int nt, int ks,
                                         int lane, float f[2]) {
    uint32_t row = nt * 8 + (lane >> 2);     // n
    uint32_t c0  = (ks * 8 + (lane & 3)) * 4;
    uint32_t s   = ((row >> 1) & 3u) << 4;
    const char* pr = base + row * 64;
    f[0] = *(const float*)(pr + (c0 ^ s));
    f[1] = *(const float*)(pr + ((c0 + 16) ^ s));
}

// ---------------------------------------------------------------------------
// tf32 mma.sync GEMM: C[M,N] = act(A[M,K] @ B^T + bias)
//   NTERMS==3: split tf32 (hi*hi + hi*lo + lo*hi) ~ fp32 accuracy
//   NTERMS==1: single-pass tf32
// Tile 128x128, BK=16, 256 threads, 8 warps (2 m x 4 n), 64x32 per warp.
// Stage (NT3): A_hi 8K @0, B_hi 8K @8K, A_lo 8K @16K, B_lo 8K @24K -> 32KB.
// Stage (NT1): A_hi @0, B_hi @8K -> 16KB. Two stages; 2 CTAs/SM.
// ---------------------------------------------------------------------------
template <int NTERMS, bool RELU, bool HASBIAS>
__global__ __launch_bounds__(256, 2)
void mma_gemm(const float* __restrict__ A, const float* __restrict__ B,
              const float* __restrict__ bias, float* __restrict__ C,
              int N, int Kd)
{
    extern __shared__ char smem[];
    constexpr int TILEB = 8192;
    constexpr int STAGE = (NTERMS == 3) ? 32768 : 16384;

    const int tid  = threadIdx.x;
    const int wid  = tid >> 5;
    const int lane = tid & 31;
    const int wm   = wid & 1;       // 0..1 -> 64 rows
    const int wn   = wid >> 1;      // 0..3 -> 32 cols

    const int nk = Kd >> 4;         // BK=16 chunks (nk even, >= 16)
    const float* Ag = A + (size_t)(blockIdx.y * 128) * Kd;
    const float* Bg = B + (size_t)(blockIdx.x * 128) * Kd;

    // staging role: thread -> (row r, 8-float half hf of the 16-wide k chunk)
    const int r  = tid >> 1;
    const int hf = tid & 1;
    const uint32_t rowoff = (uint32_t)r * 64;
    const uint32_t sw     = ((uint32_t)(r >> 1) & 3u) << 4;

    float acc[4][4][4];
#pragma unroll
    for (int i = 0; i < 4; i++)
#pragma unroll
        for (int j = 0; j < 4; j++)
#pragma unroll
            for (int q = 0; q < 4; q++) acc[i][j][q] = 0.0f;

    float4 va[2], vb[2];

    auto ldg = [&](int k0) {
        const float4* pa = (const float4*)(Ag + (size_t)r * Kd + k0 * 16 + hf * 8);
        const float4* pb = (const float4*)(Bg + (size_t)r * Kd + k0 * 16 + hf * 8);
        va[0] = pa[0]; va[1] = pa[1];
        vb[0] = pb[0]; vb[1] = pb[1];
    };

    auto stage_store = [&](int s) {
        char* st = smem + s * STAGE;
#pragma unroll
        for (int j = 0; j < 2; j++) {
            uint32_t off = rowoff + (((uint32_t)(hf * 32 + j * 16)) ^ sw);
            float4 ha = cvt4(va[j]);
            float4 hb = cvt4(vb[j]);
            *(float4*)(st + off)         = ha;
            *(float4*)(st + TILEB + off) = hb;
            if (NTERMS == 3) {
                *(float4*)(st + 2 * TILEB + off) = sub_cvt4(va[j], ha);
                *(float4*)(st + 3 * TILEB + off) = sub_cvt4(vb[j], hb);
            }
        }
    };

    ldg(0);
    stage_store(0);
    __syncthreads();

    for (int k0 = 0; k0 < nk; k0++) {
        if (k0 + 1 < nk) ldg(k0 + 1);

        const char* st = smem + (k0 & 1) * STAGE;
#pragma unroll
        for (int ks = 0; ks < 2; ks++) {
            // B fragments preloaded per ks (16 regs); A fragments short-lived per mt.
            float bh[4][2], bl[4][2];
#pragma unroll
            for (int nt = 0; nt < 4; nt++) {
                ld_bfrag(st + TILEB, wn * 4 + nt, ks, lane, bh[nt]);
                if (NTERMS == 3)
                    ld_bfrag(st + 3 * TILEB, wn * 4 + nt, ks, lane, bl[nt]);
            }
#pragma unroll
            for (int mt = 0; mt < 4; mt++) {
                float ah[4], al[4];
                ld_afrag(st, wm * 4 + mt, ks, lane, ah);
                if (NTERMS == 3)
                    ld_afrag(st + 2 * TILEB, wm * 4 + mt, ks, lane, al);
#pragma unroll
                for (int nt = 0; nt < 4; nt++) {
                    mma8(acc[mt][nt], ah, bh[nt]);
                    if (NTERMS == 3) {
                        mma8(acc[mt][nt], ah, bl[nt]);
                        mma8(acc[mt][nt], al, bh[nt]);
                    }
                }
            }
        }

        if (k0 + 1 < nk) stage_store((k0 + 1) & 1);
        __syncthreads();
    }

    // ---- epilogue ----
    const int row0 = blockIdx.y * 128 + wm * 64 + (lane >> 2);
    const int col0 = blockIdx.x * 128 + wn * 32 + (lane & 3) * 2;
#pragma unroll
    for (int mt = 0; mt < 4; mt++) {
#pragma unroll
        for (int nt = 0; nt < 4; nt++) {
            int rr = row0 + mt * 16;
            int cc = col0 + nt * 8;
            float b0 = 0.f, b1 = 0.f;
            if (HASBIAS) { b0 = __ldg(bias + cc); b1 = __ldg(bias + cc + 1); }
            float2 v0, v1;
            v0.x = acc[mt][nt][0] + b0; v0.y = acc[mt][nt][1] + b1;
            v1.x = acc[mt][nt][2] + b0; v1.y = acc[mt][nt][3] + b1;
            if (RELU) {
                v0.x = fmaxf(v0.x, 0.f); v0.y = fmaxf(v0.y, 0.f);
                v1.x = fmaxf(v1.x, 0.f); v1.y = fmaxf(v1.y, 0.f);
            }
            *(float2*)(C + (size_t)rr * N + cc)       = v0;
            *(float2*)(C + (size_t)(rr + 8) * N + cc) = v1;
        }
    }
}

// ---------------------------------------------------------------------------
// Tiled transpose: W[K,N] -> T[N,K]
// ---------------------------------------------------------------------------
__global__ __launch_bounds__(256)
void transpose_kernel(const float* __restrict__ W, float* __restrict__ T,
                      int K, int N)
{
    __shared__ float tile[32][33];
    int n0 = blockIdx.x * 32;
    int k0 = blockIdx.y * 32;
#pragma unroll
    for (int i = 0; i < 32; i += 8)
        tile[threadIdx.y + i][threadIdx.x] =
            W[(size_t)(k0 + threadIdx.y + i) * N + n0 + threadIdx.x];
    __syncthreads();
#pragma unroll
    for (int i = 0; i < 32; i += 8)
        T[(size_t)(n0 + threadIdx.y + i) * K + k0 + threadIdx.x] =
            tile[threadIdx.x][threadIdx.y + i];
}

// ---------------------------------------------------------------------------
// LayerNorm over DLAT=256, warp per row
// ---------------------------------------------------------------------------
__global__ __launch_bounds__(256)
void ln_kernel(float* __restrict__ z, const float* __restrict__ g,
               const float* __restrict__ b)
{
    int row  = blockIdx.x * 8 + (threadIdx.x >> 5);
    int lane = threadIdx.x & 31;
    float* zr = z + (size_t)row * DLAT;

    float v[8];
    float s = 0.f;
#pragma unroll
    for (int i = 0; i < 8; i++) { v[i] = zr[lane + 32 * i]; s += v[i]; }
#pragma unroll
    for (int o = 16; o; o >>= 1) s += __shfl_xor_sync(0xffffffffu, s, o);
    float mu = s * (1.0f / 256.0f);

    float s2 = 0.f;
#pragma unroll
    for (int i = 0; i < 8; i++) { float d = v[i] - mu; s2 += d * d; }
#pragma unroll
    for (int o = 16; o; o >>= 1) s2 += __shfl_xor_sync(0xffffffffu, s2, o);
    float var = s2 * (1.0f / 256.0f);
    float rs  = 1.0f / sqrtf(var + 1e-5f);

#pragma unroll
    for (int i = 0; i < 8; i++) {
        int col = lane + 32 * i;
        zr[col] = (v[i] - mu) * rs * g[col] + b[col];
    }
}

// ---------------------------------------------------------------------------
// Codebook row norms: warp per code
// ---------------------------------------------------------------------------
__global__ __launch_bounds__(256)
void cbnorm_kernel(const float* __restrict__ cb0, const float* __restrict__ cb1,
                   const float* __restrict__ cb2, float* __restrict__ cbn)
{
    int code = blockIdx.x * 8 + (threadIdx.x >> 5);
    int lane = threadIdx.x & 31;
    const float* cb = (code < KCODE) ? cb0 : (code < 2 * KCODE ? cb1 : cb2);
    const float* c  = cb + (size_t)(code & (KCODE - 1)) * DLAT;
    float s = 0.f;
#pragma unroll
    for (int i = 0; i < 8; i++) { float v = c[lane + 32 * i]; s += v * v; }
#pragma unroll
    for (int o = 16; o; o >>= 1) s += __shfl_xor_sync(0xffffffffu, s, o);
    if (lane == 0) cbn[code] = s;
}

// ---------------------------------------------------------------------------
// Argmin over K=1024 distances, first-occurrence tie-break. Warp per row.
// ---------------------------------------------------------------------------
__global__ __launch_bounds__(256)
void argmin_kernel(const float* __restrict__ res, const float* __restrict__ scores,
                   const float* __restrict__ cbn, int* __restrict__ idx_out, int stage)
{
    int row  = blockIdx.x * 8 + (threadIdx.x >> 5);
    int lane = threadIdx.x & 31;

    const float* r = res + (size_t)row * DLAT;
    float s = 0.f;
#pragma unroll
    for (int i = 0; i < 8; i++) { float v = r[lane + 32 * i]; s += v * v; }
#pragma unroll
    for (int o = 16; o; o >>= 1) s += __shfl_xor_sync(0xffffffffu, s, o);
    float rnorm = s;

    const float* sr = scores + (size_t)row * KCODE;
    float best = INFINITY;
    int bi = 0;
#pragma unroll 4
    for (int n = lane; n < KCODE; n += 32) {
        float d = (rnorm - 2.0f * sr[n]) + cbn[n];
        if (d < best) { best = d; bi = n; }
    }
#pragma unroll
    for (int o = 16; o; o >>= 1) {
        float ov = __shfl_xor_sync(0xffffffffu, best, o);
        int   oi = __shfl_xor_sync(0xffffffffu, bi, o);
        if (ov < best || (ov == best && oi < bi)) { best = ov; bi = oi; }
    }
    if (lane == 0) idx_out[row * 3 + stage] = bi;
}

// ---------------------------------------------------------------------------
// VQ update (straight-through; replicates JAX numerics)
// ---------------------------------------------------------------------------
__global__ __launch_bounds__(256)
void vq_update(float* __restrict__ res, float* __restrict__ zq,
               float* __restrict__ vloss, const float* __restrict__ cb,
               const int* __restrict__ idx, int stage)
{
    int row  = blockIdx.x * 8 + (threadIdx.x >> 5);
    int lane = threadIdx.x & 31;

    int id = idx[row * 3 + stage];
    const float* c = cb + (size_t)id * DLAT;
    float* r = res + (size_t)row * DLAT;
    float* q = zq + (size_t)row * DLAT;

    float se = 0.f;
#pragma unroll
    for (int i = 0; i < 8; i++) {
        int col = lane + 32 * i;
        float rv = r[col];
        float ev = c[col];
        float diff = rv - ev;
        se += diff * diff;
        float t   = ev - rv;
        float zqe = rv + t;
        r[col] = rv - zqe;
        q[col] = (stage == 0) ? zqe : (q[col] + zqe);
    }
#pragma unroll
    for (int o = 16; o; o >>= 1) se += __shfl_xor_sync(0xffffffffu, se, o);
    if (lane == 0) {
        float m = se * (1.0f / 256.0f);
        float l = m + 0.25f * m;
        vloss[row] = (stage == 0) ? l : (vloss[row] + l);
    }
}

// ---------------------------------------------------------------------------
// Finalize: recon loss, total loss, idx -> float
// ---------------------------------------------------------------------------
__global__ __launch_bounds__(256)
void finalize_kernel(const float* __restrict__ x, const float* __restrict__ xhat,
                     const float* __restrict__ vloss, const int* __restrict__ idx,
                     float* __restrict__ out_loss, float* __restrict__ out_idx)
{
    int row  = blockIdx.x * 8 + (threadIdx.x >> 5);
    int lane = threadIdx.x & 31;

    const float* xr = x    + (size_t)row * D_IN;
    const float* hr = xhat + (size_t)row * D_IN;
    float s = 0.f;
#pragma unroll 8
    for (int i = 0; i < 64; i++) {
        int col = lane + 32 * i;
        float d = hr[col] - xr[col];
        s += d * d;
    }
#pragma unroll
    for (int o = 16; o; o >>= 1) s += __shfl_xor_sync(0xffffffffu, s, o);
    if (lane == 0) {
        float recon = s * (1.0f / 2048.0f);
        out_loss[row] = vloss[row] + recon;
    }
    if (lane < 3) out_idx[row * 3 + lane] = (float)idx[row * 3 + lane];
}

// ---------------------------------------------------------------------------
// Launch
// ---------------------------------------------------------------------------
extern "C" void kernel_launch(void* const* d_in, const int* in_sizes, int n_in,
                              void* d_out, int out_size)
{
    const float* x      = (const float*)d_in[0];
    const float* encW1  = (const float*)d_in[1];
    const float* encb1  = (const float*)d_in[2];
    const float* encW2  = (const float*)d_in[3];
    const float* encb2  = (const float*)d_in[4];
    const float* encW3  = (const float*)d_in[5];
    const float* encb3  = (const float*)d_in[6];
    const float* ln_g   = (const float*)d_in[7];
    const float* ln_b   = (const float*)d_in[8];
    const float* cb0    = (const float*)d_in[9];
    const float* cb1    = (const float*)d_in[10];
    const float* cb2    = (const float*)d_in[11];
    const float* decW1  = (const float*)d_in[12];
    const float* decb1  = (const float*)d_in[13];
    const float* decW2  = (const float*)d_in[14];
    const float* decb2  = (const float*)d_in[15];
    const float* decW3  = (const float*)d_in[16];
    const float* decb3  = (const float*)d_in[17];

    float *h1, *h2, *res, *zq, *vloss, *cbn;
    float *w1t, *w2t, *w3t, *d1t, *d2t, *d3t;
    int* idx;
    cudaGetSymbolAddress((void**)&h1, g_h1);
    cudaGetSymbolAddress((void**)&h2, g_h2);
    cudaGetSymbolAddress((void**)&res, g_res);
    cudaGetSymbolAddress((void**)&zq, g_zq);
    cudaGetSymbolAddress((void**)&vloss, g_vloss);
    cudaGetSymbolAddress((void**)&cbn, g_cbn);
    cudaGetSymbolAddress((void**)&idx, g_idx);
    cudaGetSymbolAddress((void**)&w1t, g_w1t);
    cudaGetSymbolAddress((void**)&w2t, g_w2t);
    cudaGetSymbolAddress((void**)&w3t, g_w3t);
    cudaGetSymbolAddress((void**)&d1t, g_d1t);
    cudaGetSymbolAddress((void**)&d2t, g_d2t);
    cudaGetSymbolAddress((void**)&d3t, g_d3t);

    float* xhat     = (float*)d_out;
    float* out_loss = xhat + (size_t)BATCH * D_IN;
    float* out_idx  = out_loss + BATCH;

    const int SMEM3 = 2 * 32768;   // 64 KB -> 2 CTAs/SM
    const int SMEM1 = 2 * 16384;   // 32 KB
    cudaFuncSetAttribute((const void*)mma_gemm<3, true,  true >, cudaFuncAttributeMaxDynamicSharedMemorySize, SMEM3);
    cudaFuncSetAttribute((const void*)mma_gemm<3, false, true >, cudaFuncAttributeMaxDynamicSharedMemorySize, SMEM3);
    cudaFuncSetAttribute((const void*)mma_gemm<3, false, false>, cudaFuncAttributeMaxDynamicSharedMemorySize, SMEM3);
    cudaFuncSetAttribute((const void*)mma_gemm<1, true,  true >, cudaFuncAttributeMaxDynamicSharedMemorySize, SMEM1);
    cudaFuncSetAttribute((const void*)mma_gemm<1, false, true >, cudaFuncAttributeMaxDynamicSharedMemorySize, SMEM1);

    const dim3 blk(256);
    const dim3 tblk(32, 8);
    const int MB = BATCH / 128;          // 128
    const int warpGrid = BATCH / 8;      // 2048

    // ---- prep: transpose weights to [N,K]; codebook norms ----
    transpose_kernel<<<dim3(H1D / 32, D_IN / 32), tblk>>>(encW1, w1t, D_IN, H1D);
    transpose_kernel<<<dim3(H2D / 32, H1D / 32), tblk>>>(encW2, w2t, H1D, H2D);
    transpose_kernel<<<dim3(DLAT / 32, H2D / 32), tblk>>>(encW3, w3t, H2D, DLAT);
    transpose_kernel<<<dim3(H2D / 32, DLAT / 32), tblk>>>(decW1, d1t, DLAT, H2D);
    transpose_kernel<<<dim3(H1D / 32, H2D / 32), tblk>>>(decW2, d2t, H2D, H1D);
    transpose_kernel<<<dim3(D_IN / 32, H1D / 32), tblk>>>(decW3, d3t, H1D, D_IN);
    cbnorm_kernel<<<3 * KCODE / 8, blk>>>(cb0, cb1, cb2, cbn);

    // ---- encoder (tf32x3 split = fp32 accuracy) ----
    mma_gemm<3, true,  true ><<<dim3(H1D / 128, MB), blk, SMEM3>>>(x,  w1t, encb1, h1,  H1D,  D_IN);
    mma_gemm<3, true,  true ><<<dim3(H2D / 128, MB), blk, SMEM3>>>(h1, w2t, encb2, h2,  H2D,  H1D);
    mma_gemm<3, false, true ><<<dim3(DLAT / 128, MB), blk, SMEM3>>>(h2, w3t, encb3, res, DLAT, H2D);

    ln_kernel<<<warpGrid, blk>>>(res, ln_g, ln_b);

    // ---- residual VQ (scores in h1 scratch) ----
    for (int s = 0; s < 3; s++) {
        const float* cb = (s == 0) ? cb0 : (s == 1 ? cb1 : cb2);
        mma_gemm<3, false, false><<<dim3(KCODE / 128, MB), blk, SMEM3>>>(res, cb, nullptr, h1, KCODE, DLAT);
        argmin_kernel<<<warpGrid, blk>>>(res, h1, cbn + s * KCODE, idx, s);
        vq_update<<<warpGrid, blk>>>(res, zq, vloss, cb, idx, s);
    }

    // ---- decoder (single-pass tf32; post-argmin, tolerance-safe) ----
    mma_gemm<1, true,  true ><<<dim3(H2D / 128, MB), blk, SMEM1>>>(zq, d1t, decb1, h2,   H2D,  DLAT);
    mma_gemm<1, true,  true ><<<dim3(H1D / 128, MB), blk, SMEM1>>>(h2, d2t, decb2, h1,   H1D,  H2D);
    mma_gemm<1, false, true ><<<dim3(D_IN / 128, MB), blk, SMEM1>>>(h1, d3t, decb3, xhat, D_IN, H1D);

    finalize_kernel<<<warpGrid, blk>>>(x, xhat, vloss, idx, out_loss, out_idx);
}